// round 9
// baseline (speedup 1.0000x reference)
#include <cuda_runtime.h>
#include <cuda_bf16.h>
#include <cstdint>

#define MAX_N 100000
#define MAX_E 1700000
#define FDIM  128
#define CHUNK 1024

// Scratch (allocation-free: __device__ globals)
__device__ float g_H[(size_t)MAX_N * FDIM];
__device__ __nv_bfloat16 g_xhi[(size_t)MAX_N * FDIM];
__device__ __nv_bfloat16 g_xlo[(size_t)MAX_N * FDIM];
__device__ __nv_bfloat16 g_wthi[3 * FDIM * FDIM];   // transposed [n][k]
__device__ __nv_bfloat16 g_wtlo[3 * FDIM * FDIM];
__device__ float g_dinv[MAX_N];
__device__ float g_dinv2[MAX_N];
__device__ int   g_cnt[MAX_N];
__device__ int   g_pos[MAX_N];
__device__ int   g_rowStart[MAX_N];
__device__ int   g_wcur[MAX_N];
__device__ int   g_chunkSum[256];
__device__ int   g_es[MAX_E];
__device__ float g_en[MAX_E];

__device__ __forceinline__ void split_bf16(float x, __nv_bfloat16& hi, __nv_bfloat16& lo) {
    hi = __float2bfloat16(x);
    lo = __float2bfloat16(x - __bfloat162float(hi));
}

// ---------------------------------------------------------------------------
__global__ void k_hist(const int* __restrict__ ei, int E) {
    int e = blockIdx.x * blockDim.x + threadIdx.x;
    if (e < E) atomicAdd(&g_cnt[ei[E + e]], 1);
}

__global__ __launch_bounds__(256) void k_scan1(int n) {
    __shared__ int sh[256];
    int t = threadIdx.x;
    int base = blockIdx.x * CHUNK + t * 4;
    int v0 = (base + 0 < n) ? g_cnt[base + 0] : 0;
    int v1 = (base + 1 < n) ? g_cnt[base + 1] : 0;
    int v2 = (base + 2 < n) ? g_cnt[base + 2] : 0;
    int v3 = (base + 3 < n) ? g_cnt[base + 3] : 0;
    int tsum = v0 + v1 + v2 + v3;
    sh[t] = tsum;
    __syncthreads();
    for (int off = 1; off < 256; off <<= 1) {
        int x = (t >= off) ? sh[t - off] : 0;
        __syncthreads();
        sh[t] += x;
        __syncthreads();
    }
    int texcl = sh[t] - tsum;
    if (base + 0 < n) g_pos[base + 0] = texcl;
    if (base + 1 < n) g_pos[base + 1] = texcl + v0;
    if (base + 2 < n) g_pos[base + 2] = texcl + v0 + v1;
    if (base + 3 < n) g_pos[base + 3] = texcl + v0 + v1 + v2;
    if (t == 255) g_chunkSum[blockIdx.x] = sh[255];
}

__global__ __launch_bounds__(256) void k_scan2(int nChunks) {
    __shared__ int sh[256];
    int t = threadIdx.x;
    int v = (t < nChunks) ? g_chunkSum[t] : 0;
    sh[t] = v;
    __syncthreads();
    for (int off = 1; off < 256; off <<= 1) {
        int x = (t >= off) ? sh[t - off] : 0;
        __syncthreads();
        sh[t] += x;
        __syncthreads();
    }
    if (t < nChunks) g_chunkSum[t] = sh[t] - v;
}

__global__ void k_scan3(int n) {
    int i = blockIdx.x * blockDim.x + threadIdx.x;
    if (i < n) {
        int rs = g_pos[i] + g_chunkSum[i / CHUNK];
        g_rowStart[i] = rs;
        g_wcur[i]     = rs;
        float di = rsqrtf((float)g_cnt[i] + 1.0f);
        g_dinv[i]  = di;
        g_dinv2[i] = di * di;
    }
}

__global__ void k_build(const int* __restrict__ ei, int E) {
    int e = blockIdx.x * blockDim.x + threadIdx.x;
    if (e < E) {
        int s = ei[e];
        int d = ei[E + e];
        int p = atomicAdd(&g_wcur[d], 1);
        g_es[p] = s;
        g_en[p] = g_dinv[s] * g_dinv[d];
    }
}

// ---------------------------------------------------------------------------
__global__ void k_convertX(const float* __restrict__ x, long long n8) {
    long long i = (long long)blockIdx.x * blockDim.x + threadIdx.x;
    if (i >= n8) return;
    const float4* xp = (const float4*)x + i * 2;
    float4 v0 = __ldg(xp), v1 = __ldg(xp + 1);
    float f[8] = {v0.x, v0.y, v0.z, v0.w, v1.x, v1.y, v1.z, v1.w};
    __nv_bfloat16 hi[8], lo[8];
#pragma unroll
    for (int j = 0; j < 8; j++) split_bf16(f[j], hi[j], lo[j]);
    *(uint4*)&g_xhi[i * 8] = *(uint4*)hi;
    *(uint4*)&g_xlo[i * 8] = *(uint4*)lo;
}

// All three W's in one launch: grid=192, slot = blockIdx.x/64
__global__ void k_convertW(const float* __restrict__ W1,
                           const float* __restrict__ W2,
                           const float* __restrict__ W3) {
    int slot = blockIdx.x >> 6;
    const float* W = (slot == 0) ? W1 : (slot == 1) ? W2 : W3;
    int idx = ((blockIdx.x & 63) << 8) + threadIdx.x;  // 0..16383
    int n = idx >> 7, k = idx & 127;
    __nv_bfloat16 hi, lo;
    split_bf16(__ldg(&W[k * FDIM + n]), hi, lo);
    g_wthi[slot * FDIM * FDIM + idx] = hi;
    g_wtlo[slot * FDIM * FDIM + idx] = lo;
}

// ---------------------------------------------------------------------------
// MMA helpers
__device__ __forceinline__ void ldsm4(uint32_t* r, uint32_t addr) {
    asm volatile("ldmatrix.sync.aligned.m8n8.x4.shared.b16 {%0,%1,%2,%3}, [%4];"
        : "=r"(r[0]), "=r"(r[1]), "=r"(r[2]), "=r"(r[3]) : "r"(addr));
}
__device__ __forceinline__ void mma16816(float* c, const uint32_t* a, const uint32_t* b) {
    asm volatile(
        "mma.sync.aligned.m16n8k16.row.col.f32.bf16.bf16.f32 "
        "{%0,%1,%2,%3}, {%4,%5,%6,%7}, {%8,%9}, {%0,%1,%2,%3};"
        : "+f"(c[0]), "+f"(c[1]), "+f"(c[2]), "+f"(c[3])
        : "r"(a[0]), "r"(a[1]), "r"(a[2]), "r"(a[3]), "r"(b[0]), "r"(b[1]));
}

// ---------------------------------------------------------------------------
// Tensor-core GEMM, FULL K=128 resident in smem: one fill, one sync,
// 8 uninterrupted k16 mma steps. Block tile 128x128, 8 warps (4m x 2n).
#define APK 136                          // row stride in bf16 elems (128+8)
#define ASTRIDE (128 * APK)              // elems per array
#define SMEM_BYTES (4 * ASTRIDE * 2)     // 139264 B

__global__ __launch_bounds__(256) void k_gemm(
    const __nv_bfloat16* __restrict__ Xhi, const __nv_bfloat16* __restrict__ Xlo,
    const __nv_bfloat16* __restrict__ Wthi, const __nv_bfloat16* __restrict__ Wtlo,
    int N)
{
    extern __shared__ __nv_bfloat16 sm[];
    __nv_bfloat16* AH = sm;
    __nv_bfloat16* AL = sm + ASTRIDE;
    __nv_bfloat16* BH = sm + 2 * ASTRIDE;
    __nv_bfloat16* BL = sm + 3 * ASTRIDE;

    int t    = threadIdx.x;
    int wid  = t >> 5;
    int lane = t & 31;
    int warp_m = wid & 3;
    int warp_n = wid >> 2;
    int rowbase = blockIdx.x * 128;

    // Fill: 128 rows x 128 k per array; 2048 uint4 per array, 8 per thread.
#pragma unroll
    for (int i = 0; i < 8; i++) {
        int idx = t + i * 256;          // 0..2047
        int row = idx >> 4;             // 0..127 (16 uint4 per 128-bf16 row)
        int k8  = (idx & 15) * 8;       // 0,8,...,120
        int so  = row * APK + k8;
        int grow = rowbase + row;
        uint4 vh, vl;
        if (grow < N) {
            size_t off = (size_t)grow * FDIM + k8;
            vh = *(const uint4*)&Xhi[off];
            vl = *(const uint4*)&Xlo[off];
        } else {
            vh = make_uint4(0, 0, 0, 0);
            vl = make_uint4(0, 0, 0, 0);
        }
        *(uint4*)&AH[so] = vh;
        *(uint4*)&AL[so] = vl;
        size_t boff = (size_t)row * FDIM + k8;   // row = n
        *(uint4*)&BH[so] = *(const uint4*)&Wthi[boff];
        *(uint4*)&BL[so] = *(const uint4*)&Wtlo[boff];
    }
    __syncthreads();

    float acc[2][8][4];
#pragma unroll
    for (int i = 0; i < 2; i++)
#pragma unroll
        for (int j = 0; j < 8; j++)
#pragma unroll
            for (int q = 0; q < 4; q++) acc[i][j][q] = 0.f;

#pragma unroll
    for (int s = 0; s < 8; s++) {
        int kb = s * 16;
        uint32_t ah[2][4], al[2][4];
#pragma unroll
        for (int mi = 0; mi < 2; mi++) {
            int mrow = warp_m * 32 + mi * 16 + (lane & 15);
            int kcol = kb + ((lane >> 4) << 3);
            int so = mrow * APK + kcol;
            ldsm4(ah[mi], (uint32_t)__cvta_generic_to_shared(AH + so));
            ldsm4(al[mi], (uint32_t)__cvta_generic_to_shared(AL + so));
        }
        uint32_t bh[8][2], bl[8][2];
#pragma unroll
        for (int nb = 0; nb < 4; nb++) {
            int nrow = warp_n * 64 + nb * 16 + ((lane >> 4) << 3) + (lane & 7);
            int kcol = kb + (((lane >> 3) & 1) << 3);
            int so = nrow * APK + kcol;
            uint32_t r[4];
            ldsm4(r, (uint32_t)__cvta_generic_to_shared(BH + so));
            bh[nb*2][0] = r[0]; bh[nb*2][1] = r[1];
            bh[nb*2+1][0] = r[2]; bh[nb*2+1][1] = r[3];
            ldsm4(r, (uint32_t)__cvta_generic_to_shared(BL + so));
            bl[nb*2][0] = r[0]; bl[nb*2][1] = r[1];
            bl[nb*2+1][0] = r[2]; bl[nb*2+1][1] = r[3];
        }
#pragma unroll
        for (int mi = 0; mi < 2; mi++)
#pragma unroll
            for (int nj = 0; nj < 8; nj++) {
                mma16816(acc[mi][nj], ah[mi], bh[nj]);
                mma16816(acc[mi][nj], ah[mi], bl[nj]);
                mma16816(acc[mi][nj], al[mi], bh[nj]);
            }
    }

#pragma unroll
    for (int mi = 0; mi < 2; mi++) {
        int r0 = rowbase + warp_m * 32 + mi * 16 + (lane >> 2);
        int r1 = r0 + 8;
#pragma unroll
        for (int nj = 0; nj < 8; nj++) {
            int col = warp_n * 64 + nj * 8 + 2 * (lane & 3);
            if (r0 < N)
                *(float2*)&g_H[(size_t)r0 * FDIM + col] =
                    make_float2(acc[mi][nj][0], acc[mi][nj][1]);
            if (r1 < N)
                *(float2*)&g_H[(size_t)r1 * FDIM + col] =
                    make_float2(acc[mi][nj][2], acc[mi][nj][3]);
        }
    }
}

// ---------------------------------------------------------------------------
// Pull-based aggregation + self-loop + bias + relu, fused.
// mode 0: write bf16 hi/lo split into g_xhi/g_xlo (feeds next GEMM), relu.
// mode 1: write fp32 to ofp (final layer), no relu.
__global__ __launch_bounds__(256) void k_gather(
    const float* __restrict__ h, const float* __restrict__ b,
    float* __restrict__ ofp, int N, int mode)
{
    int warp = (blockIdx.x * 256 + threadIdx.x) >> 5;
    int lane = threadIdx.x & 31;
    if (warp >= N) return;

    int row   = warp;
    int start = g_rowStart[row];
    int cnt   = g_cnt[row];

    float d2 = g_dinv2[row];
    float4 acc = __ldg((const float4*)(h + (size_t)row * FDIM) + lane);
    acc.x *= d2; acc.y *= d2; acc.z *= d2; acc.w *= d2;

    for (int e0 = 0; e0 < cnt; e0 += 32) {
        int mye = e0 + lane;
        int s = 0; float nm = 0.f;
        if (mye < cnt) {
            s  = __ldg(&g_es[start + mye]);
            nm = __ldg(&g_en[start + mye]);
        }
        int m = min(32, cnt - e0);
#pragma unroll 8
        for (int j = 0; j < m; j++) {
            int   sj = __shfl_sync(0xffffffffu, s,  j);
            float nj = __shfl_sync(0xffffffffu, nm, j);
            float4 v = __ldg((const float4*)(h + (size_t)sj * FDIM) + lane);
            acc.x = fmaf(v.x, nj, acc.x);
            acc.y = fmaf(v.y, nj, acc.y);
            acc.z = fmaf(v.z, nj, acc.z);
            acc.w = fmaf(v.w, nj, acc.w);
        }
    }

    float4 bb = __ldg((const float4*)b + lane);
    acc.x += bb.x; acc.y += bb.y; acc.z += bb.z; acc.w += bb.w;

    if (mode == 0) {
        float f[4];
        f[0] = fmaxf(acc.x, 0.f); f[1] = fmaxf(acc.y, 0.f);
        f[2] = fmaxf(acc.z, 0.f); f[3] = fmaxf(acc.w, 0.f);
        __nv_bfloat16 hi[4], lo[4];
#pragma unroll
        for (int j = 0; j < 4; j++) split_bf16(f[j], hi[j], lo[j]);
        size_t off = (size_t)row * FDIM + lane * 4;
        *(uint2*)&g_xhi[off] = *(uint2*)hi;
        *(uint2*)&g_xlo[off] = *(uint2*)lo;
    } else {
        ((float4*)(ofp + (size_t)row * FDIM))[lane] = acc;
    }
}

// ---------------------------------------------------------------------------
extern "C" void kernel_launch(void* const* d_in, const int* in_sizes, int n_in,
                              void* d_out, int out_size)
{
    const float* x  = (const float*)d_in[0];
    const int*   ei = (const int*)d_in[1];   // int32 (JAX x64 disabled)
    const float* W1 = (const float*)d_in[2];
    const float* b1 = (const float*)d_in[3];
    const float* W2 = (const float*)d_in[4];
    const float* b2 = (const float*)d_in[5];
    const float* W3 = (const float*)d_in[6];
    const float* b3 = (const float*)d_in[7];
    float* out = (float*)d_out;

    int N = in_sizes[0] / FDIM;
    int E = in_sizes[1] / 2;

    float* H;
    cudaGetSymbolAddress((void**)&H, g_H);
    __nv_bfloat16 *XHI, *XLO, *WTHI, *WTLO;
    cudaGetSymbolAddress((void**)&XHI,  g_xhi);
    cudaGetSymbolAddress((void**)&XLO,  g_xlo);
    cudaGetSymbolAddress((void**)&WTHI, g_wthi);
    cudaGetSymbolAddress((void**)&WTLO, g_wtlo);
    int* CNT;
    cudaGetSymbolAddress((void**)&CNT, g_cnt);

    cudaFuncSetAttribute(k_gemm, cudaFuncAttributeMaxDynamicSharedMemorySize, SMEM_BYTES);

    int nThr = 256;
    int nBlkN    = (N + nThr - 1) / nThr;
    int nBlkE    = (E + nThr - 1) / nThr;
    int nBlkGemm = (N + 127) / 128;
    int nChunks  = (N + CHUNK - 1) / CHUNK;
    long long gthreads = (long long)N * 32;
    int nBlkGather = (int)((gthreads + nThr - 1) / nThr);
    long long n8 = (long long)N * FDIM / 8;
    int nBlkConv = (int)((n8 + nThr - 1) / nThr);

    // --- one-time per launch: conversions + CSR build ---
    k_convertX<<<nBlkConv, nThr>>>(x, n8);
    k_convertW<<<192, nThr>>>(W1, W2, W3);

    cudaMemsetAsync(CNT, 0, (size_t)N * sizeof(int));
    k_hist<<<nBlkE, nThr>>>(ei, E);
    k_scan1<<<nChunks, nThr>>>(N);
    k_scan2<<<1, nThr>>>(nChunks);
    k_scan3<<<nBlkN, nThr>>>(N);
    k_build<<<nBlkE, nThr>>>(ei, E);

    const int WSZ = FDIM * FDIM;
    // Layer 1
    k_gemm<<<nBlkGemm, nThr, SMEM_BYTES>>>(XHI, XLO, WTHI, WTLO, N);
    k_gather<<<nBlkGather, nThr>>>(H, b1, nullptr, N, 0);

    // Layer 2
    k_gemm<<<nBlkGemm, nThr, SMEM_BYTES>>>(XHI, XLO, WTHI + WSZ, WTLO + WSZ, N);
    k_gather<<<nBlkGather, nThr>>>(H, b2, nullptr, N, 0);

    // Layer 3: fp32 out, no relu
    k_gemm<<<nBlkGemm, nThr, SMEM_BYTES>>>(XHI, XLO, WTHI + 2*WSZ, WTLO + 2*WSZ, N);
    k_gather<<<nBlkGather, nThr>>>(H, b3, out, N, 1);
}

// round 10
// speedup vs baseline: 1.1851x; 1.1851x over previous
#include <cuda_runtime.h>
#include <cuda_fp16.h>
#include <cstdint>

#define MAX_N 100000
#define MAX_E 1700000
#define FDIM  128
#define CHUNK 1024

// Scratch (allocation-free: __device__ globals)
__device__ float  g_H[(size_t)MAX_N * FDIM];
__device__ __half g_xh[(size_t)MAX_N * FDIM];
__device__ __half g_wt[3 * FDIM * FDIM];   // transposed [n][k], fp16
__device__ float g_dinv[MAX_N];
__device__ float g_dinv2[MAX_N];
__device__ int   g_cnt[MAX_N];
__device__ int   g_pos[MAX_N];
__device__ int   g_rowStart[MAX_N];
__device__ int   g_wcur[MAX_N];
__device__ int   g_chunkSum[256];
__device__ int   g_es[MAX_E];
__device__ float g_en[MAX_E];

// ---------------------------------------------------------------------------
__global__ void k_hist(const int* __restrict__ ei, int E) {
    int e = blockIdx.x * blockDim.x + threadIdx.x;
    if (e < E) atomicAdd(&g_cnt[ei[E + e]], 1);
}

__global__ __launch_bounds__(256) void k_scan1(int n) {
    __shared__ int sh[256];
    int t = threadIdx.x;
    int base = blockIdx.x * CHUNK + t * 4;
    int v0 = (base + 0 < n) ? g_cnt[base + 0] : 0;
    int v1 = (base + 1 < n) ? g_cnt[base + 1] : 0;
    int v2 = (base + 2 < n) ? g_cnt[base + 2] : 0;
    int v3 = (base + 3 < n) ? g_cnt[base + 3] : 0;
    int tsum = v0 + v1 + v2 + v3;
    sh[t] = tsum;
    __syncthreads();
    for (int off = 1; off < 256; off <<= 1) {
        int x = (t >= off) ? sh[t - off] : 0;
        __syncthreads();
        sh[t] += x;
        __syncthreads();
    }
    int texcl = sh[t] - tsum;
    if (base + 0 < n) g_pos[base + 0] = texcl;
    if (base + 1 < n) g_pos[base + 1] = texcl + v0;
    if (base + 2 < n) g_pos[base + 2] = texcl + v0 + v1;
    if (base + 3 < n) g_pos[base + 3] = texcl + v0 + v1 + v2;
    if (t == 255) g_chunkSum[blockIdx.x] = sh[255];
}

__global__ __launch_bounds__(256) void k_scan2(int nChunks) {
    __shared__ int sh[256];
    int t = threadIdx.x;
    int v = (t < nChunks) ? g_chunkSum[t] : 0;
    sh[t] = v;
    __syncthreads();
    for (int off = 1; off < 256; off <<= 1) {
        int x = (t >= off) ? sh[t - off] : 0;
        __syncthreads();
        sh[t] += x;
        __syncthreads();
    }
    if (t < nChunks) g_chunkSum[t] = sh[t] - v;
}

__global__ void k_scan3(int n) {
    int i = blockIdx.x * blockDim.x + threadIdx.x;
    if (i < n) {
        int rs = g_pos[i] + g_chunkSum[i / CHUNK];
        g_rowStart[i] = rs;
        g_wcur[i]     = rs;
        float di = rsqrtf((float)g_cnt[i] + 1.0f);
        g_dinv[i]  = di;
        g_dinv2[i] = di * di;
    }
}

__global__ void k_build(const int* __restrict__ ei, int E) {
    int e = blockIdx.x * blockDim.x + threadIdx.x;
    if (e < E) {
        int s = ei[e];
        int d = ei[E + e];
        int p = atomicAdd(&g_wcur[d], 1);
        g_es[p] = s;
        g_en[p] = g_dinv[s] * g_dinv[d];
    }
}

// ---------------------------------------------------------------------------
// Convert x (fp32) -> fp16. 8 floats per thread.
__global__ void k_convertX(const float* __restrict__ x, long long n8) {
    long long i = (long long)blockIdx.x * blockDim.x + threadIdx.x;
    if (i >= n8) return;
    const float4* xp = (const float4*)x + i * 2;
    float4 v0 = __ldg(xp), v1 = __ldg(xp + 1);
    float f[8] = {v0.x, v0.y, v0.z, v0.w, v1.x, v1.y, v1.z, v1.w};
    __half h[8];
#pragma unroll
    for (int j = 0; j < 8; j++) h[j] = __float2half_rn(f[j]);
    *(uint4*)&g_xh[i * 8] = *(uint4*)h;
}

// All three W's in one launch: grid=192, slot = blockIdx.x/64
__global__ void k_convertW(const float* __restrict__ W1,
                           const float* __restrict__ W2,
                           const float* __restrict__ W3) {
    int slot = blockIdx.x >> 6;
    const float* W = (slot == 0) ? W1 : (slot == 1) ? W2 : W3;
    int idx = ((blockIdx.x & 63) << 8) + threadIdx.x;  // 0..16383
    int n = idx >> 7, k = idx & 127;
    g_wt[slot * FDIM * FDIM + idx] = __float2half_rn(__ldg(&W[k * FDIM + n]));
}

// ---------------------------------------------------------------------------
// MMA helpers
__device__ __forceinline__ void ldsm4(uint32_t* r, uint32_t addr) {
    asm volatile("ldmatrix.sync.aligned.m8n8.x4.shared.b16 {%0,%1,%2,%3}, [%4];"
        : "=r"(r[0]), "=r"(r[1]), "=r"(r[2]), "=r"(r[3]) : "r"(addr));
}
__device__ __forceinline__ void mma16816(float* c, const uint32_t* a, const uint32_t* b) {
    asm volatile(
        "mma.sync.aligned.m16n8k16.row.col.f32.f16.f16.f32 "
        "{%0,%1,%2,%3}, {%4,%5,%6,%7}, {%8,%9}, {%0,%1,%2,%3};"
        : "+f"(c[0]), "+f"(c[1]), "+f"(c[2]), "+f"(c[3])
        : "r"(a[0]), "r"(a[1]), "r"(a[2]), "r"(a[3]), "r"(b[0]), "r"(b[1]));
}

// ---------------------------------------------------------------------------
// Tensor-core GEMM, fp16 operands, fp32 accum: h = X @ W.
// R7-proven structure: 128x128 tile, K chunks of 32, 8 warps (4m x 2n),
// static smem, 2 CTAs/SM.
#define APAD 40
__global__ __launch_bounds__(256) void k_gemm(
    const __half* __restrict__ Xh, const __half* __restrict__ Wt, int N)
{
    __shared__ __half a_s[128][APAD];
    __shared__ __half b_s[128][APAD];   // [n][k]

    int t    = threadIdx.x;
    int wid  = t >> 5;
    int lane = t & 31;
    int warp_m = wid & 3;
    int warp_n = wid >> 2;
    int rowbase = blockIdx.x * 128;

    float acc[2][8][4];
#pragma unroll
    for (int i = 0; i < 2; i++)
#pragma unroll
        for (int j = 0; j < 8; j++)
#pragma unroll
            for (int q = 0; q < 4; q++) acc[i][j][q] = 0.f;

    for (int kc = 0; kc < 128; kc += 32) {
        // A fill: 128 rows x 32 k = 512 uint4, 2 per thread.
#pragma unroll
        for (int i = 0; i < 2; i++) {
            int idx = t + i * 256;
            int row = idx >> 2;
            int k8  = (idx & 3) * 8;
            int grow = rowbase + row;
            uint4 v = (grow < N)
                ? *(const uint4*)&Xh[(size_t)grow * FDIM + kc + k8]
                : make_uint4(0, 0, 0, 0);
            *(uint4*)&a_s[row][k8] = v;
            // B fill (transposed W: row = n)
            *(uint4*)&b_s[row][k8] =
                *(const uint4*)&Wt[(size_t)row * FDIM + kc + k8];
        }
        __syncthreads();

#pragma unroll
        for (int s = 0; s < 2; s++) {
            int kb = s * 16;
            uint32_t af[2][4];
#pragma unroll
            for (int mi = 0; mi < 2; mi++) {
                int mrow = warp_m * 32 + mi * 16 + (lane & 15);
                int kcol = kb + ((lane >> 4) << 3);
                ldsm4(af[mi], (uint32_t)__cvta_generic_to_shared(&a_s[mrow][kcol]));
            }
            uint32_t bf[8][2];
#pragma unroll
            for (int nb = 0; nb < 4; nb++) {
                int nrow = warp_n * 64 + nb * 16 + ((lane >> 4) << 3) + (lane & 7);
                int kcol = kb + (((lane >> 3) & 1) << 3);
                uint32_t r[4];
                ldsm4(r, (uint32_t)__cvta_generic_to_shared(&b_s[nrow][kcol]));
                bf[nb*2][0] = r[0]; bf[nb*2][1] = r[1];
                bf[nb*2+1][0] = r[2]; bf[nb*2+1][1] = r[3];
            }
#pragma unroll
            for (int mi = 0; mi < 2; mi++)
#pragma unroll
                for (int nj = 0; nj < 8; nj++)
                    mma16816(acc[mi][nj], af[mi], bf[nj]);
        }
        __syncthreads();
    }

#pragma unroll
    for (int mi = 0; mi < 2; mi++) {
        int r0 = rowbase + warp_m * 32 + mi * 16 + (lane >> 2);
        int r1 = r0 + 8;
#pragma unroll
        for (int nj = 0; nj < 8; nj++) {
            int col = warp_n * 64 + nj * 8 + 2 * (lane & 3);
            if (r0 < N)
                *(float2*)&g_H[(size_t)r0 * FDIM + col] =
                    make_float2(acc[mi][nj][0], acc[mi][nj][1]);
            if (r1 < N)
                *(float2*)&g_H[(size_t)r1 * FDIM + col] =
                    make_float2(acc[mi][nj][2], acc[mi][nj][3]);
        }
    }
}

// ---------------------------------------------------------------------------
// Pull-based aggregation + self-loop + bias + relu, fused.
// mode 0: write fp16 into g_xh (feeds next GEMM), relu.
// mode 1: write fp32 to ofp (final layer), no relu.
__global__ __launch_bounds__(256) void k_gather(
    const float* __restrict__ h, const float* __restrict__ b,
    float* __restrict__ ofp, int N, int mode)
{
    int warp = (blockIdx.x * 256 + threadIdx.x) >> 5;
    int lane = threadIdx.x & 31;
    if (warp >= N) return;

    int row   = warp;
    int start = g_rowStart[row];
    int cnt   = g_cnt[row];

    float d2 = g_dinv2[row];
    float4 acc = __ldg((const float4*)(h + (size_t)row * FDIM) + lane);
    acc.x *= d2; acc.y *= d2; acc.z *= d2; acc.w *= d2;

    for (int e0 = 0; e0 < cnt; e0 += 32) {
        int mye = e0 + lane;
        int s = 0; float nm = 0.f;
        if (mye < cnt) {
            s  = __ldg(&g_es[start + mye]);
            nm = __ldg(&g_en[start + mye]);
        }
        int m = min(32, cnt - e0);
#pragma unroll 8
        for (int j = 0; j < m; j++) {
            int   sj = __shfl_sync(0xffffffffu, s,  j);
            float nj = __shfl_sync(0xffffffffu, nm, j);
            float4 v = __ldg((const float4*)(h + (size_t)sj * FDIM) + lane);
            acc.x = fmaf(v.x, nj, acc.x);
            acc.y = fmaf(v.y, nj, acc.y);
            acc.z = fmaf(v.z, nj, acc.z);
            acc.w = fmaf(v.w, nj, acc.w);
        }
    }

    float4 bb = __ldg((const float4*)b + lane);
    acc.x += bb.x; acc.y += bb.y; acc.z += bb.z; acc.w += bb.w;

    if (mode == 0) {
        __half hh[4];
        hh[0] = __float2half_rn(fmaxf(acc.x, 0.f));
        hh[1] = __float2half_rn(fmaxf(acc.y, 0.f));
        hh[2] = __float2half_rn(fmaxf(acc.z, 0.f));
        hh[3] = __float2half_rn(fmaxf(acc.w, 0.f));
        *(uint2*)&g_xh[(size_t)row * FDIM + lane * 4] = *(uint2*)hh;
    } else {
        ((float4*)(ofp + (size_t)row * FDIM))[lane] = acc;
    }
}

// ---------------------------------------------------------------------------
extern "C" void kernel_launch(void* const* d_in, const int* in_sizes, int n_in,
                              void* d_out, int out_size)
{
    const float* x  = (const float*)d_in[0];
    const int*   ei = (const int*)d_in[1];   // int32 (JAX x64 disabled)
    const float* W1 = (const float*)d_in[2];
    const float* b1 = (const float*)d_in[3];
    const float* W2 = (const float*)d_in[4];
    const float* b2 = (const float*)d_in[5];
    const float* W3 = (const float*)d_in[6];
    const float* b3 = (const float*)d_in[7];
    float* out = (float*)d_out;

    int N = in_sizes[0] / FDIM;
    int E = in_sizes[1] / 2;

    float* H;
    cudaGetSymbolAddress((void**)&H, g_H);
    __half *XH, *WT;
    cudaGetSymbolAddress((void**)&XH, g_xh);
    cudaGetSymbolAddress((void**)&WT, g_wt);
    int* CNT;
    cudaGetSymbolAddress((void**)&CNT, g_cnt);

    int nThr = 256;
    int nBlkN    = (N + nThr - 1) / nThr;
    int nBlkE    = (E + nThr - 1) / nThr;
    int nBlkGemm = (N + 127) / 128;
    int nChunks  = (N + CHUNK - 1) / CHUNK;
    long long gthreads = (long long)N * 32;
    int nBlkGather = (int)((gthreads + nThr - 1) / nThr);
    long long n8 = (long long)N * FDIM / 8;
    int nBlkConv = (int)((n8 + nThr - 1) / nThr);

    // --- one-time per launch: conversions + CSR build ---
    k_convertX<<<nBlkConv, nThr>>>(x, n8);
    k_convertW<<<192, nThr>>>(W1, W2, W3);

    cudaMemsetAsync(CNT, 0, (size_t)N * sizeof(int));
    k_hist<<<nBlkE, nThr>>>(ei, E);
    k_scan1<<<nChunks, nThr>>>(N);
    k_scan2<<<1, nThr>>>(nChunks);
    k_scan3<<<nBlkN, nThr>>>(N);
    k_build<<<nBlkE, nThr>>>(ei, E);

    const int WSZ = FDIM * FDIM;
    // Layer 1
    k_gemm<<<nBlkGemm, nThr>>>(XH, WT, N);
    k_gather<<<nBlkGather, nThr>>>(H, b1, nullptr, N, 0);

    // Layer 2
    k_gemm<<<nBlkGemm, nThr>>>(XH, WT + WSZ, N);
    k_gather<<<nBlkGather, nThr>>>(H, b2, nullptr, N, 0);

    // Layer 3: fp32 out, no relu
    k_gemm<<<nBlkGemm, nThr>>>(XH, WT + 2*WSZ, N);
    k_gather<<<nBlkGather, nThr>>>(H, b3, out, N, 1);
}

// round 11
// speedup vs baseline: 1.4986x; 1.2645x over previous
#include <cuda_runtime.h>
#include <cuda_fp16.h>
#include <cstdint>

#define MAX_N 100000
#define MAX_E 1700000
#define FDIM  128
#define CHUNK 1024

// Scratch (allocation-free: __device__ globals)
__device__ __half g_hh[(size_t)MAX_N * FDIM];   // H in fp16
__device__ __half g_xh[(size_t)MAX_N * FDIM];   // GEMM input, fp16
__device__ __half g_wt[3 * FDIM * FDIM];        // W transposed [n][k], fp16
__device__ float g_dinv[MAX_N];
__device__ float g_dinv2[MAX_N];
__device__ int   g_cnt[MAX_N];
__device__ int   g_pos[MAX_N];
__device__ int   g_rowStart[MAX_N];
__device__ int   g_wcur[MAX_N];
__device__ int   g_chunkSum[256];
__device__ int   g_es[MAX_E];
__device__ float g_en[MAX_E];

// ---------------------------------------------------------------------------
__global__ void k_hist(const int* __restrict__ ei, int E) {
    int e = blockIdx.x * blockDim.x + threadIdx.x;
    if (e < E) atomicAdd(&g_cnt[ei[E + e]], 1);
}

__global__ __launch_bounds__(256) void k_scan1(int n) {
    __shared__ int sh[256];
    int t = threadIdx.x;
    int base = blockIdx.x * CHUNK + t * 4;
    int v0 = (base + 0 < n) ? g_cnt[base + 0] : 0;
    int v1 = (base + 1 < n) ? g_cnt[base + 1] : 0;
    int v2 = (base + 2 < n) ? g_cnt[base + 2] : 0;
    int v3 = (base + 3 < n) ? g_cnt[base + 3] : 0;
    int tsum = v0 + v1 + v2 + v3;
    sh[t] = tsum;
    __syncthreads();
    for (int off = 1; off < 256; off <<= 1) {
        int x = (t >= off) ? sh[t - off] : 0;
        __syncthreads();
        sh[t] += x;
        __syncthreads();
    }
    int texcl = sh[t] - tsum;
    if (base + 0 < n) g_pos[base + 0] = texcl;
    if (base + 1 < n) g_pos[base + 1] = texcl + v0;
    if (base + 2 < n) g_pos[base + 2] = texcl + v0 + v1;
    if (base + 3 < n) g_pos[base + 3] = texcl + v0 + v1 + v2;
    if (t == 255) g_chunkSum[blockIdx.x] = sh[255];
}

__global__ __launch_bounds__(256) void k_scan2(int nChunks) {
    __shared__ int sh[256];
    int t = threadIdx.x;
    int v = (t < nChunks) ? g_chunkSum[t] : 0;
    sh[t] = v;
    __syncthreads();
    for (int off = 1; off < 256; off <<= 1) {
        int x = (t >= off) ? sh[t - off] : 0;
        __syncthreads();
        sh[t] += x;
        __syncthreads();
    }
    if (t < nChunks) g_chunkSum[t] = sh[t] - v;
}

__global__ void k_scan3(int n) {
    int i = blockIdx.x * blockDim.x + threadIdx.x;
    if (i < n) {
        int rs = g_pos[i] + g_chunkSum[i / CHUNK];
        g_rowStart[i] = rs;
        g_wcur[i]     = rs;
        float di = rsqrtf((float)g_cnt[i] + 1.0f);
        g_dinv[i]  = di;
        g_dinv2[i] = di * di;
    }
}

__global__ void k_build(const int* __restrict__ ei, int E) {
    int e = blockIdx.x * blockDim.x + threadIdx.x;
    if (e < E) {
        int s = ei[e];
        int d = ei[E + e];
        int p = atomicAdd(&g_wcur[d], 1);
        g_es[p] = s;
        g_en[p] = g_dinv[s] * g_dinv[d];
    }
}

// ---------------------------------------------------------------------------
__global__ void k_convertX(const float* __restrict__ x, long long n8) {
    long long i = (long long)blockIdx.x * blockDim.x + threadIdx.x;
    if (i >= n8) return;
    const float4* xp = (const float4*)x + i * 2;
    float4 v0 = __ldg(xp), v1 = __ldg(xp + 1);
    float f[8] = {v0.x, v0.y, v0.z, v0.w, v1.x, v1.y, v1.z, v1.w};
    __half h[8];
#pragma unroll
    for (int j = 0; j < 8; j++) h[j] = __float2half_rn(f[j]);
    *(uint4*)&g_xh[i * 8] = *(uint4*)h;
}

__global__ void k_convertW(const float* __restrict__ W1,
                           const float* __restrict__ W2,
                           const float* __restrict__ W3) {
    int slot = blockIdx.x >> 6;
    const float* W = (slot == 0) ? W1 : (slot == 1) ? W2 : W3;
    int idx = ((blockIdx.x & 63) << 8) + threadIdx.x;
    int n = idx >> 7, k = idx & 127;
    g_wt[slot * FDIM * FDIM + idx] = __float2half_rn(__ldg(&W[k * FDIM + n]));
}

// ---------------------------------------------------------------------------
// MMA helpers
__device__ __forceinline__ void ldsm4(uint32_t* r, uint32_t addr) {
    asm volatile("ldmatrix.sync.aligned.m8n8.x4.shared.b16 {%0,%1,%2,%3}, [%4];"
        : "=r"(r[0]), "=r"(r[1]), "=r"(r[2]), "=r"(r[3]) : "r"(addr));
}
__device__ __forceinline__ void mma16816(float* c, const uint32_t* a, const uint32_t* b) {
    asm volatile(
        "mma.sync.aligned.m16n8k16.row.col.f32.f16.f16.f32 "
        "{%0,%1,%2,%3}, {%4,%5,%6,%7}, {%8,%9}, {%0,%1,%2,%3};"
        : "+f"(c[0]), "+f"(c[1]), "+f"(c[2]), "+f"(c[3])
        : "r"(a[0]), "r"(a[1]), "r"(a[2]), "r"(a[3]), "r"(b[0]), "r"(b[1]));
}

// ---------------------------------------------------------------------------
// Tensor-core GEMM, fp16 in / fp16 out (fp32 accum): h = X @ W.
// 128x128 tile, K chunks of 32, 8 warps (4m x 2n), 2 CTAs/SM.
#define APAD 40
__global__ __launch_bounds__(256) void k_gemm(
    const __half* __restrict__ Xh, const __half* __restrict__ Wt, int N)
{
    __shared__ __half a_s[128][APAD];
    __shared__ __half b_s[128][APAD];   // [n][k]

    int t    = threadIdx.x;
    int wid  = t >> 5;
    int lane = t & 31;
    int warp_m = wid & 3;
    int warp_n = wid >> 2;
    int rowbase = blockIdx.x * 128;

    float acc[2][8][4];
#pragma unroll
    for (int i = 0; i < 2; i++)
#pragma unroll
        for (int j = 0; j < 8; j++)
#pragma unroll
            for (int q = 0; q < 4; q++) acc[i][j][q] = 0.f;

    for (int kc = 0; kc < 128; kc += 32) {
#pragma unroll
        for (int i = 0; i < 2; i++) {
            int idx = t + i * 256;
            int row = idx >> 2;
            int k8  = (idx & 3) * 8;
            int grow = rowbase + row;
            uint4 v = (grow < N)
                ? *(const uint4*)&Xh[(size_t)grow * FDIM + kc + k8]
                : make_uint4(0, 0, 0, 0);
            *(uint4*)&a_s[row][k8] = v;
            *(uint4*)&b_s[row][k8] =
                *(const uint4*)&Wt[(size_t)row * FDIM + kc + k8];
        }
        __syncthreads();

#pragma unroll
        for (int s = 0; s < 2; s++) {
            int kb = s * 16;
            uint32_t af[2][4];
#pragma unroll
            for (int mi = 0; mi < 2; mi++) {
                int mrow = warp_m * 32 + mi * 16 + (lane & 15);
                int kcol = kb + ((lane >> 4) << 3);
                ldsm4(af[mi], (uint32_t)__cvta_generic_to_shared(&a_s[mrow][kcol]));
            }
            uint32_t bf[8][2];
#pragma unroll
            for (int nb = 0; nb < 4; nb++) {
                int nrow = warp_n * 64 + nb * 16 + ((lane >> 4) << 3) + (lane & 7);
                int kcol = kb + (((lane >> 3) & 1) << 3);
                uint32_t r[4];
                ldsm4(r, (uint32_t)__cvta_generic_to_shared(&b_s[nrow][kcol]));
                bf[nb*2][0] = r[0]; bf[nb*2][1] = r[1];
                bf[nb*2+1][0] = r[2]; bf[nb*2+1][1] = r[3];
            }
#pragma unroll
            for (int mi = 0; mi < 2; mi++)
#pragma unroll
                for (int nj = 0; nj < 8; nj++)
                    mma16816(acc[mi][nj], af[mi], bf[nj]);
        }
        __syncthreads();
    }

    // Epilogue: store H as fp16 (half2 per c-pair)
#pragma unroll
    for (int mi = 0; mi < 2; mi++) {
        int r0 = rowbase + warp_m * 32 + mi * 16 + (lane >> 2);
        int r1 = r0 + 8;
#pragma unroll
        for (int nj = 0; nj < 8; nj++) {
            int col = warp_n * 64 + nj * 8 + 2 * (lane & 3);
            if (r0 < N) {
                __half2 p = __floats2half2_rn(acc[mi][nj][0], acc[mi][nj][1]);
                *(__half2*)&g_hh[(size_t)r0 * FDIM + col] = p;
            }
            if (r1 < N) {
                __half2 p = __floats2half2_rn(acc[mi][nj][2], acc[mi][nj][3]);
                *(__half2*)&g_hh[(size_t)r1 * FDIM + col] = p;
            }
        }
    }
}

// ---------------------------------------------------------------------------
// Pull-based aggregation + self-loop + bias + relu, fused. H is fp16.
// Lane l owns floats [4l, 4l+4) => 4 halves = uint2 per row.
// mode 0: write fp16 into g_xh (feeds next GEMM), relu.
// mode 1: write fp32 to ofp (final layer), no relu.
__global__ __launch_bounds__(256) void k_gather(
    const __half* __restrict__ h, const float* __restrict__ b,
    float* __restrict__ ofp, int N, int mode)
{
    int warp = (blockIdx.x * 256 + threadIdx.x) >> 5;
    int lane = threadIdx.x & 31;
    if (warp >= N) return;

    int row   = warp;
    int start = g_rowStart[row];
    int cnt   = g_cnt[row];

    float d2 = g_dinv2[row];
    uint2 hv = __ldg((const uint2*)(h + (size_t)row * FDIM) + lane);
    float2 p0 = __half22float2(*(__half2*)&hv.x);
    float2 p1 = __half22float2(*(__half2*)&hv.y);
    float4 acc = make_float4(p0.x * d2, p0.y * d2, p1.x * d2, p1.y * d2);

    for (int e0 = 0; e0 < cnt; e0 += 32) {
        int mye = e0 + lane;
        int s = 0; float nm = 0.f;
        if (mye < cnt) {
            s  = __ldg(&g_es[start + mye]);
            nm = __ldg(&g_en[start + mye]);
        }
        int m = min(32, cnt - e0);
#pragma unroll 8
        for (int j = 0; j < m; j++) {
            int   sj = __shfl_sync(0xffffffffu, s,  j);
            float nj = __shfl_sync(0xffffffffu, nm, j);
            uint2 v = __ldg((const uint2*)(h + (size_t)sj * FDIM) + lane);
            float2 q0 = __half22float2(*(__half2*)&v.x);
            float2 q1 = __half22float2(*(__half2*)&v.y);
            acc.x = fmaf(q0.x, nj, acc.x);
            acc.y = fmaf(q0.y, nj, acc.y);
            acc.z = fmaf(q1.x, nj, acc.z);
            acc.w = fmaf(q1.y, nj, acc.w);
        }
    }

    float4 bb = __ldg((const float4*)b + lane);
    acc.x += bb.x; acc.y += bb.y; acc.z += bb.z; acc.w += bb.w;

    if (mode == 0) {
        __half hh[4];
        hh[0] = __float2half_rn(fmaxf(acc.x, 0.f));
        hh[1] = __float2half_rn(fmaxf(acc.y, 0.f));
        hh[2] = __float2half_rn(fmaxf(acc.z, 0.f));
        hh[3] = __float2half_rn(fmaxf(acc.w, 0.f));
        *(uint2*)&g_xh[(size_t)row * FDIM + lane * 4] = *(uint2*)hh;
    } else {
        ((float4*)(ofp + (size_t)row * FDIM))[lane] = acc;
    }
}

// ---------------------------------------------------------------------------
extern "C" void kernel_launch(void* const* d_in, const int* in_sizes, int n_in,
                              void* d_out, int out_size)
{
    const float* x  = (const float*)d_in[0];
    const int*   ei = (const int*)d_in[1];   // int32 (JAX x64 disabled)
    const float* W1 = (const float*)d_in[2];
    const float* b1 = (const float*)d_in[3];
    const float* W2 = (const float*)d_in[4];
    const float* b2 = (const float*)d_in[5];
    const float* W3 = (const float*)d_in[6];
    const float* b3 = (const float*)d_in[7];
    float* out = (float*)d_out;

    int N = in_sizes[0] / FDIM;
    int E = in_sizes[1] / 2;

    __half *HH, *XH, *WT;
    cudaGetSymbolAddress((void**)&HH, g_hh);
    cudaGetSymbolAddress((void**)&XH, g_xh);
    cudaGetSymbolAddress((void**)&WT, g_wt);
    int* CNT;
    cudaGetSymbolAddress((void**)&CNT, g_cnt);

    int nThr = 256;
    int nBlkN    = (N + nThr - 1) / nThr;
    int nBlkE    = (E + nThr - 1) / nThr;
    int nBlkGemm = (N + 127) / 128;
    int nChunks  = (N + CHUNK - 1) / CHUNK;
    long long gthreads = (long long)N * 32;
    int nBlkGather = (int)((gthreads + nThr - 1) / nThr);
    long long n8 = (long long)N * FDIM / 8;
    int nBlkConv = (int)((n8 + nThr - 1) / nThr);

    // --- one-time per launch: conversions + CSR build ---
    k_convertX<<<nBlkConv, nThr>>>(x, n8);
    k_convertW<<<192, nThr>>>(W1, W2, W3);

    cudaMemsetAsync(CNT, 0, (size_t)N * sizeof(int));
    k_hist<<<nBlkE, nThr>>>(ei, E);
    k_scan1<<<nChunks, nThr>>>(N);
    k_scan2<<<1, nThr>>>(nChunks);
    k_scan3<<<nBlkN, nThr>>>(N);
    k_build<<<nBlkE, nThr>>>(ei, E);

    const int WSZ = FDIM * FDIM;
    // Layer 1
    k_gemm<<<nBlkGemm, nThr>>>(XH, WT, N);
    k_gather<<<nBlkGather, nThr>>>(HH, b1, nullptr, N, 0);

    // Layer 2
    k_gemm<<<nBlkGemm, nThr>>>(XH, WT + WSZ, N);
    k_gather<<<nBlkGather, nThr>>>(HH, b2, nullptr, N, 0);

    // Layer 3: fp32 out, no relu
    k_gemm<<<nBlkGemm, nThr>>>(XH, WT + 2*WSZ, N);
    k_gather<<<nBlkGather, nThr>>>(HH, b3, out, N, 1);
}

// round 12
// speedup vs baseline: 1.6270x; 1.0857x over previous
#include <cuda_runtime.h>
#include <cuda_fp16.h>
#include <cstdint>

#define MAX_N 100000
#define MAX_E 1700000
#define FDIM  128
#define CHUNK 1024

// Scratch (allocation-free: __device__ globals)
__device__ __half g_hh[(size_t)MAX_N * FDIM];   // H in fp16
__device__ __half g_xh[(size_t)MAX_N * FDIM];   // GEMM input, fp16
__device__ __half g_wt[3 * FDIM * FDIM];        // W transposed [n][k], fp16
__device__ float g_dinv[MAX_N];
__device__ float g_dinv2[MAX_N];
__device__ int   g_cnt[MAX_N];
__device__ int   g_pos[MAX_N];
__device__ int   g_rowStart[MAX_N];
__device__ int   g_wcur[MAX_N];
__device__ int   g_chunkSum[128];
__device__ int2  g_epk[MAX_E];                  // packed (src, norm-bits)

// ---------------------------------------------------------------------------
__global__ void k_hist(const int* __restrict__ ei, int E) {
    int e = blockIdx.x * blockDim.x + threadIdx.x;
    if (e < E) atomicAdd(&g_cnt[ei[E + e]], 1);
}

__global__ __launch_bounds__(256) void k_scan1(int n) {
    __shared__ int sh[256];
    int t = threadIdx.x;
    int base = blockIdx.x * CHUNK + t * 4;
    int v0 = (base + 0 < n) ? g_cnt[base + 0] : 0;
    int v1 = (base + 1 < n) ? g_cnt[base + 1] : 0;
    int v2 = (base + 2 < n) ? g_cnt[base + 2] : 0;
    int v3 = (base + 3 < n) ? g_cnt[base + 3] : 0;
    int tsum = v0 + v1 + v2 + v3;
    sh[t] = tsum;
    __syncthreads();
    for (int off = 1; off < 256; off <<= 1) {
        int x = (t >= off) ? sh[t - off] : 0;
        __syncthreads();
        sh[t] += x;
        __syncthreads();
    }
    int texcl = sh[t] - tsum;
    if (base + 0 < n) g_pos[base + 0] = texcl;
    if (base + 1 < n) g_pos[base + 1] = texcl + v0;
    if (base + 2 < n) g_pos[base + 2] = texcl + v0 + v1;
    if (base + 3 < n) g_pos[base + 3] = texcl + v0 + v1 + v2;
    if (t == 255) g_chunkSum[blockIdx.x] = sh[255];
}

// Merged scan2+scan3: each block re-scans the (<=128) chunk sums in smem,
// then finalizes rowStart/cursors/dinv for its 256 nodes.
__global__ __launch_bounds__(256) void k_scan23(int n, int nChunks) {
    __shared__ int cs[128];
    int t = threadIdx.x;
    if (t < 128) cs[t] = (t < nChunks) ? g_chunkSum[t] : 0;
    __syncthreads();
    if (t < 128) {
        // Hillis-Steele inclusive over 128 (single-warp-free simple version)
        for (int off = 1; off < 128; off <<= 1) {
            int x = (t >= off) ? cs[t - off] : 0;
            __syncthreads();
            cs[t] += x;
            __syncthreads();
        }
    } else {
        for (int off = 1; off < 128; off <<= 1) { __syncthreads(); __syncthreads(); }
    }
    int i = blockIdx.x * 256 + t;
    if (i < n) {
        int c = i / CHUNK;
        int chunkExcl = (c == 0) ? 0 : cs[c - 1];
        int rs = g_pos[i] + chunkExcl;
        g_rowStart[i] = rs;
        g_wcur[i]     = rs;
        float di = rsqrtf((float)g_cnt[i] + 1.0f);
        g_dinv[i]  = di;
        g_dinv2[i] = di * di;
    }
}

__global__ void k_build(const int* __restrict__ ei, int E) {
    int e = blockIdx.x * blockDim.x + threadIdx.x;
    if (e < E) {
        int s = ei[e];
        int d = ei[E + e];
        int p = atomicAdd(&g_wcur[d], 1);
        g_epk[p] = make_int2(s, __float_as_int(g_dinv[s] * g_dinv[d]));
    }
}

// ---------------------------------------------------------------------------
__global__ void k_convertX(const float* __restrict__ x, long long n8) {
    long long i = (long long)blockIdx.x * blockDim.x + threadIdx.x;
    if (i >= n8) return;
    const float4* xp = (const float4*)x + i * 2;
    float4 v0 = __ldg(xp), v1 = __ldg(xp + 1);
    float f[8] = {v0.x, v0.y, v0.z, v0.w, v1.x, v1.y, v1.z, v1.w};
    __half h[8];
#pragma unroll
    for (int j = 0; j < 8; j++) h[j] = __float2half_rn(f[j]);
    *(uint4*)&g_xh[i * 8] = *(uint4*)h;
}

__global__ void k_convertW(const float* __restrict__ W1,
                           const float* __restrict__ W2,
                           const float* __restrict__ W3) {
    int slot = blockIdx.x >> 6;
    const float* W = (slot == 0) ? W1 : (slot == 1) ? W2 : W3;
    int idx = ((blockIdx.x & 63) << 8) + threadIdx.x;
    int n = idx >> 7, k = idx & 127;
    g_wt[slot * FDIM * FDIM + idx] = __float2half_rn(__ldg(&W[k * FDIM + n]));
}

// ---------------------------------------------------------------------------
// MMA helpers
__device__ __forceinline__ void ldsm4(uint32_t* r, uint32_t addr) {
    asm volatile("ldmatrix.sync.aligned.m8n8.x4.shared.b16 {%0,%1,%2,%3}, [%4];"
        : "=r"(r[0]), "=r"(r[1]), "=r"(r[2]), "=r"(r[3]) : "r"(addr));
}
__device__ __forceinline__ void mma16816(float* c, const uint32_t* a, const uint32_t* b) {
    asm volatile(
        "mma.sync.aligned.m16n8k16.row.col.f32.f16.f16.f32 "
        "{%0,%1,%2,%3}, {%4,%5,%6,%7}, {%8,%9}, {%0,%1,%2,%3};"
        : "+f"(c[0]), "+f"(c[1]), "+f"(c[2]), "+f"(c[3])
        : "r"(a[0]), "r"(a[1]), "r"(a[2]), "r"(a[3]), "r"(b[0]), "r"(b[1]));
}

// ---------------------------------------------------------------------------
// Tensor-core GEMM, fp16 in / fp16 out (fp32 accum): h = X @ W.
#define APAD 40
__global__ __launch_bounds__(256) void k_gemm(
    const __half* __restrict__ Xh, const __half* __restrict__ Wt, int N)
{
    __shared__ __half a_s[128][APAD];
    __shared__ __half b_s[128][APAD];   // [n][k]

    int t    = threadIdx.x;
    int wid  = t >> 5;
    int lane = t & 31;
    int warp_m = wid & 3;
    int warp_n = wid >> 2;
    int rowbase = blockIdx.x * 128;

    float acc[2][8][4];
#pragma unroll
    for (int i = 0; i < 2; i++)
#pragma unroll
        for (int j = 0; j < 8; j++)
#pragma unroll
            for (int q = 0; q < 4; q++) acc[i][j][q] = 0.f;

    for (int kc = 0; kc < 128; kc += 32) {
#pragma unroll
        for (int i = 0; i < 2; i++) {
            int idx = t + i * 256;
            int row = idx >> 2;
            int k8  = (idx & 3) * 8;
            int grow = rowbase + row;
            uint4 v = (grow < N)
                ? *(const uint4*)&Xh[(size_t)grow * FDIM + kc + k8]
                : make_uint4(0, 0, 0, 0);
            *(uint4*)&a_s[row][k8] = v;
            *(uint4*)&b_s[row][k8] =
                *(const uint4*)&Wt[(size_t)row * FDIM + kc + k8];
        }
        __syncthreads();

#pragma unroll
        for (int s = 0; s < 2; s++) {
            int kb = s * 16;
            uint32_t af[2][4];
#pragma unroll
            for (int mi = 0; mi < 2; mi++) {
                int mrow = warp_m * 32 + mi * 16 + (lane & 15);
                int kcol = kb + ((lane >> 4) << 3);
                ldsm4(af[mi], (uint32_t)__cvta_generic_to_shared(&a_s[mrow][kcol]));
            }
            uint32_t bf[8][2];
#pragma unroll
            for (int nb = 0; nb < 4; nb++) {
                int nrow = warp_n * 64 + nb * 16 + ((lane >> 4) << 3) + (lane & 7);
                int kcol = kb + (((lane >> 3) & 1) << 3);
                uint32_t r[4];
                ldsm4(r, (uint32_t)__cvta_generic_to_shared(&b_s[nrow][kcol]));
                bf[nb*2][0] = r[0]; bf[nb*2][1] = r[1];
                bf[nb*2+1][0] = r[2]; bf[nb*2+1][1] = r[3];
            }
#pragma unroll
            for (int mi = 0; mi < 2; mi++)
#pragma unroll
                for (int nj = 0; nj < 8; nj++)
                    mma16816(acc[mi][nj], af[mi], bf[nj]);
        }
        __syncthreads();
    }

#pragma unroll
    for (int mi = 0; mi < 2; mi++) {
        int r0 = rowbase + warp_m * 32 + mi * 16 + (lane >> 2);
        int r1 = r0 + 8;
#pragma unroll
        for (int nj = 0; nj < 8; nj++) {
            int col = warp_n * 64 + nj * 8 + 2 * (lane & 3);
            if (r0 < N) {
                __half2 p = __floats2half2_rn(acc[mi][nj][0], acc[mi][nj][1]);
                *(__half2*)&g_hh[(size_t)r0 * FDIM + col] = p;
            }
            if (r1 < N) {
                __half2 p = __floats2half2_rn(acc[mi][nj][2], acc[mi][nj][3]);
                *(__half2*)&g_hh[(size_t)r1 * FDIM + col] = p;
            }
        }
    }
}

// ---------------------------------------------------------------------------
// Pull-based aggregation + self-loop + bias + relu, fused. H fp16, edges int2.
__global__ __launch_bounds__(256) void k_gather(
    const __half* __restrict__ h, const float* __restrict__ b,
    float* __restrict__ ofp, int N, int mode)
{
    int warp = (blockIdx.x * 256 + threadIdx.x) >> 5;
    int lane = threadIdx.x & 31;
    if (warp >= N) return;

    int row   = warp;
    int start = g_rowStart[row];
    int cnt   = g_cnt[row];

    float d2 = g_dinv2[row];
    uint2 hv = __ldg((const uint2*)(h + (size_t)row * FDIM) + lane);
    float2 p0 = __half22float2(*(__half2*)&hv.x);
    float2 p1 = __half22float2(*(__half2*)&hv.y);
    float4 acc = make_float4(p0.x * d2, p0.y * d2, p1.x * d2, p1.y * d2);

    for (int e0 = 0; e0 < cnt; e0 += 32) {
        int mye = e0 + lane;
        int s = 0; float nm = 0.f;
        if (mye < cnt) {
            int2 ep = __ldg(&g_epk[start + mye]);
            s  = ep.x;
            nm = __int_as_float(ep.y);
        }
        int m = min(32, cnt - e0);
#pragma unroll 8
        for (int j = 0; j < m; j++) {
            int   sj = __shfl_sync(0xffffffffu, s,  j);
            float nj = __shfl_sync(0xffffffffu, nm, j);
            uint2 v = __ldg((const uint2*)(h + (size_t)sj * FDIM) + lane);
            float2 q0 = __half22float2(*(__half2*)&v.x);
            float2 q1 = __half22float2(*(__half2*)&v.y);
            acc.x = fmaf(q0.x, nj, acc.x);
            acc.y = fmaf(q0.y, nj, acc.y);
            acc.z = fmaf(q1.x, nj, acc.z);
            acc.w = fmaf(q1.y, nj, acc.w);
        }
    }

    float4 bb = __ldg((const float4*)b + lane);
    acc.x += bb.x; acc.y += bb.y; acc.z += bb.z; acc.w += bb.w;

    if (mode == 0) {
        __half hh[4];
        hh[0] = __float2half_rn(fmaxf(acc.x, 0.f));
        hh[1] = __float2half_rn(fmaxf(acc.y, 0.f));
        hh[2] = __float2half_rn(fmaxf(acc.z, 0.f));
        hh[3] = __float2half_rn(fmaxf(acc.w, 0.f));
        *(uint2*)&g_xh[(size_t)row * FDIM + lane * 4] = *(uint2*)hh;
    } else {
        ((float4*)(ofp + (size_t)row * FDIM))[lane] = acc;
    }
}

// ---------------------------------------------------------------------------
extern "C" void kernel_launch(void* const* d_in, const int* in_sizes, int n_in,
                              void* d_out, int out_size)
{
    const float* x  = (const float*)d_in[0];
    const int*   ei = (const int*)d_in[1];   // int32 (JAX x64 disabled)
    const float* W1 = (const float*)d_in[2];
    const float* b1 = (const float*)d_in[3];
    const float* W2 = (const float*)d_in[4];
    const float* b2 = (const float*)d_in[5];
    const float* W3 = (const float*)d_in[6];
    const float* b3 = (const float*)d_in[7];
    float* out = (float*)d_out;

    int N = in_sizes[0] / FDIM;
    int E = in_sizes[1] / 2;

    __half *HH, *XH, *WT;
    cudaGetSymbolAddress((void**)&HH, g_hh);
    cudaGetSymbolAddress((void**)&XH, g_xh);
    cudaGetSymbolAddress((void**)&WT, g_wt);
    int* CNT;
    cudaGetSymbolAddress((void**)&CNT, g_cnt);

    int nThr = 256;
    int nBlkN    = (N + nThr - 1) / nThr;
    int nBlkE    = (E + nThr - 1) / nThr;
    int nBlkGemm = (N + 127) / 128;
    int nChunks  = (N + CHUNK - 1) / CHUNK;
    long long gthreads = (long long)N * 32;
    int nBlkGather = (int)((gthreads + nThr - 1) / nThr);
    long long n8 = (long long)N * FDIM / 8;
    int nBlkConv = (int)((n8 + nThr - 1) / nThr);
    const int WSZ = FDIM * FDIM;

    // Fork-join: branch A (converts + gemm1) runs parallel to branch B (CSR).
    cudaStream_t s2;
    cudaStreamCreateWithFlags(&s2, cudaStreamNonBlocking);
    cudaEvent_t evFork, evA;
    cudaEventCreateWithFlags(&evFork, cudaEventDisableTiming);
    cudaEventCreateWithFlags(&evA, cudaEventDisableTiming);

    cudaEventRecord(evFork, 0);
    cudaStreamWaitEvent(s2, evFork, 0);

    // Branch A (s2): convertX -> convertW -> gemm1
    k_convertX<<<nBlkConv, nThr, 0, s2>>>(x, n8);
    k_convertW<<<192, nThr, 0, s2>>>(W1, W2, W3);
    k_gemm<<<nBlkGemm, nThr, 0, s2>>>(XH, WT, N);
    cudaEventRecord(evA, s2);

    // Branch B (default stream): CSR build
    cudaMemsetAsync(CNT, 0, (size_t)N * sizeof(int));
    k_hist<<<nBlkE, nThr>>>(ei, E);
    k_scan1<<<nChunks, nThr>>>(N);
    k_scan23<<<nBlkN, nThr>>>(N, nChunks);
    k_build<<<nBlkE, nThr>>>(ei, E);

    // Join
    cudaStreamWaitEvent(0, evA, 0);

    // Layer 1 gather
    k_gather<<<nBlkGather, nThr>>>(HH, b1, nullptr, N, 0);

    // Layer 2
    k_gemm<<<nBlkGemm, nThr>>>(XH, WT + WSZ, N);
    k_gather<<<nBlkGather, nThr>>>(HH, b2, nullptr, N, 0);

    // Layer 3: fp32 out, no relu
    k_gemm<<<nBlkGemm, nThr>>>(XH, WT + 2*WSZ, N);
    k_gather<<<nBlkGather, nThr>>>(HH, b3, out, N, 1);

    cudaEventDestroy(evFork);
    cudaEventDestroy(evA);
    cudaStreamDestroy(s2);
}